// round 6
// baseline (speedup 1.0000x reference)
#include <cuda_runtime.h>
#include <math.h>

#define GRID   128
#define NT     512
#define COLS   16
#define H      2048
#define D      16
#define TMAX   4096
#define OUTN   128
#define WSTRIDE ((size_t)2049 * 2048)

// Persistent device state (no allocation).
// g_flagv[c] = t+2  <=>  CTA c has finished step t (h(t+1) slice visible). Init 1 = "h(0) ready".
__device__ __align__(128) int g_flagv[GRID];
__device__ unsigned g_bar2;    // epilogue logits barrier (one-time, atomic OK)
__device__ __align__(16) float g_h[2][H];
__device__ float g_logits[OUTN];

__global__ void awk_init_kernel(const float* __restrict__ h0) {
    int i = blockIdx.x * blockDim.x + threadIdx.x;
    if (i < H) g_h[0][i] = h0[i];
    if (i < GRID) g_flagv[i] = 1;
    if (i == 0) g_bar2 = 0u;
}

__device__ __forceinline__ int ld_acq(const int* p) {
    int v;
    asm volatile("ld.acquire.gpu.b32 %0, [%1];" : "=r"(v) : "l"(p) : "memory");
    return v;
}
__device__ __forceinline__ void st_rel(int* p, int v) {
    asm volatile("st.release.gpu.b32 [%0], %1;" :: "l"(p), "r"(v) : "memory");
}
__device__ __forceinline__ unsigned ld_acq_u(const unsigned* p) {
    unsigned v;
    asm volatile("ld.acquire.gpu.u32 %0, [%1];" : "=r"(v) : "l"(p) : "memory");
    return v;
}

#define FMA2(acc, hh, ww) \
    asm("fma.rn.f32x2 %0, %1, %2, %3;" : "=l"(acc) : "l"(hh), "l"(ww), "l"(acc))
#define UNPK(fx, fy, a) \
    asm("mov.b64 {%0, %1}, %2;" : "=f"(fx), "=f"(fy) : "l"(a))

__global__ __launch_bounds__(NT, 1)
void awk_kernel(const float* __restrict__ x_in,    // [4096]
                const float* __restrict__ h0,      // [2048]
                const float* __restrict__ Wg,      // [16, 2049, 2048]
                const float* __restrict__ bg,      // [16, 2048]
                const float* __restrict__ Wo,      // [2048, 128]
                const float* __restrict__ bo,      // [128]
                const int*   __restrict__ markers, // [16]
                float* __restrict__ outp, int out_size)
{
    __shared__ float x_sm[TMAX];                 // input scalars; reused for final h
    __shared__ float h_sm[16 * 136];             // per-warp padded h chunks
    __shared__ float red_sm[2][256];             // step-parity double-buffered partials
    __shared__ __align__(16) float h_self_sm[16];// own CTA's freshest h slice
    __shared__ int   cum_sm[D + 4];

    const int tid   = threadIdx.x;
    const int bid   = blockIdx.x;
    const int lane  = tid & 31;
    const int wrp   = tid >> 5;
    const int c     = tid & 15;     // column within CTA
    const int s     = tid >> 4;     // k-segment 0..31 (64 k-values each)
    const int jbase = bid * COLS;

    for (int i = tid; i < TMAX; i += NT) x_sm[i] = x_in[i];
    if (tid == 0) {
        int a = 0;
        for (int l = 0; l < D; l++) { a += markers[l]; cum_sm[l] = a; }
        cum_sm[D] = (a < TMAX) ? a : TMAX;
    }
    if (tid < COLS) h_self_sm[tid] = h0[jbase + tid];   // self slice of h(0)
    __syncthreads();
    const int S = cum_sm[D];

    // poll lane bookkeeping (warp 0): this lane watches flags {lane, +32, +64, +96}
    const bool own0 = (lane        == bid);
    const bool own1 = (lane + 32   == bid);
    const bool own2 = (lane + 64   == bid);
    const bool own3 = (lane + 96   == bid);
    const bool self_ld = (wrp == (bid >> 3)) && ((lane >> 2) == (bid & 7));

    unsigned long long w2[32];     // 64 weights packed as 32 f32x2
    float w0 = 0.f, bb = 0.f;
    int layer = 0, next_b = 0;

    for (int step = 0; step < S; ++step) {
        // ---- layer switch: refill register weights (64B-coalesced direct LDG) ----
        if (step == next_b) {
            while (step >= cum_sm[layer]) layer++;
            next_b = cum_sm[layer];
            const float* Wl = Wg + (size_t)layer * WSTRIDE + 2048 + jbase + c;
            #pragma unroll 8
            for (int q = 0; q < 32; q++) {
                float wa = Wl[(size_t)(64 * s + 2 * q)     * 2048];
                float wb = Wl[(size_t)(64 * s + 2 * q + 1) * 2048];
                asm("mov.b64 %0, {%1, %2};" : "=l"(w2[q]) : "f"(wa), "f"(wb));
            }
            if (tid < COLS) {
                w0 = Wg[(size_t)layer * WSTRIDE + jbase + tid];
                bb = bg[layer * H + jbase + tid];
            }
        }

        // ---- detect: warp 0 scans all 128 flags in one coalesced acquire read ----
        if (wrp == 0) {
            const int tgt = step + 1;
            bool ok;
            do {
                int f0 = ld_acq(&g_flagv[lane]);
                int f1 = ld_acq(&g_flagv[lane + 32]);
                int f2 = ld_acq(&g_flagv[lane + 64]);
                int f3 = ld_acq(&g_flagv[lane + 96]);
                ok = (own0 || f0 >= tgt) && (own1 || f1 >= tgt) &&
                     (own2 || f2 >= tgt) && (own3 || f3 >= tgt);
            } while (!__all_sync(0xffffffffu, ok));
        }
        __syncthreads();                       // (A) release detection CTA-wide

        const int buf = step & 1;

        // ---- warp-private h chunk -> SMEM; own slice comes from SMEM directly ----
        {
            float4 hv;
            if (self_ld) hv = *(const float4*)(&h_self_sm[(lane & 3) * 4]);
            else         hv = __ldcg((const float4*)(g_h[buf] + wrp * 128 + lane * 4));
            *(float4*)(&h_sm[wrp * 136 + (lane >> 4) * 68 + (lane & 15) * 4]) = hv;
        }
        __syncwarp();

        // ---- partial dot: 32 packed f32x2 FMAs, 16 LDS.128 ----
        unsigned long long a0 = 0ull, a1 = 0ull, a2 = 0ull, a3 = 0ull;
        const ulonglong2* hp = (const ulonglong2*)(&h_sm[wrp * 136 + (s & 1) * 68]);
        #pragma unroll
        for (int q = 0; q < 16; q++) {
            ulonglong2 hq = hp[q];
            if (q & 1) { FMA2(a2, hq.x, w2[2 * q]); FMA2(a3, hq.y, w2[2 * q + 1]); }
            else       { FMA2(a0, hq.x, w2[2 * q]); FMA2(a1, hq.y, w2[2 * q + 1]); }
        }
        float f0x, f0y, f1x, f1y, f2x, f2y, f3x, f3y;
        UNPK(f0x, f0y, a0); UNPK(f1x, f1y, a1);
        UNPK(f2x, f2y, a2); UNPK(f3x, f3y, a3);
        float acc = ((f0x + f0y) + (f1x + f1y)) + ((f2x + f2y) + (f3x + f3y));

        acc += __shfl_xor_sync(0xffffffffu, acc, 16);
        if (lane < 16) red_sm[buf][wrp * 16 + lane] = acc;
        __syncthreads();                       // (B) partials ready; h reads done

        // ---- final reduce + relu + publish (warp 0, 32 lanes; release store arrival) ----
        if (wrp == 0) {
            const int half = lane >> 4;
            float v = 0.f;
            #pragma unroll
            for (int wi = 0; wi < 8; wi++) v += red_sm[buf][(half * 8 + wi) * 16 + c];
            v += __shfl_xor_sync(0xffffffffu, v, 16);
            if (lane < 16) {
                v = fmaf(x_sm[step], w0, v) + bb;
                v = fmaxf(v, 0.f);
                g_h[buf ^ 1][jbase + lane] = v;
                h_self_sm[lane] = v;           // freshest self slice for next step
            }
            __syncwarp();
            if (lane == 0) st_rel(&g_flagv[bid], step + 2);   // distinct address: no RMW
        }
    }

    // ======== epilogue ========
    if (wrp == 0) {
        const int tgt = S + 1;
        bool ok;
        do {
            int f0 = ld_acq(&g_flagv[lane]);
            int f1 = ld_acq(&g_flagv[lane + 32]);
            int f2 = ld_acq(&g_flagv[lane + 64]);
            int f3 = ld_acq(&g_flagv[lane + 96]);
            ok = (f0 >= tgt) && (f1 >= tgt) && (f2 >= tgt) && (f3 >= tgt);
        } while (!__all_sync(0xffffffffu, ok));
    }
    __syncthreads();
    {
        const int buf = S & 1;
        float4 hv = __ldcg((const float4*)(g_h[buf] + wrp * 128 + lane * 4));
        *(float4*)(&x_sm[wrp * 128 + lane * 4]) = hv;   // full final h, contiguous
    }
    __syncthreads();

    // logit for output o = bid  (GRID == OUTN)
    float p = 0.f;
    #pragma unroll
    for (int r = 0; r < H / NT; r++) {
        int i = r * NT + tid;
        p += x_sm[i] * Wo[(size_t)i * OUTN + bid];
    }
    p += __shfl_xor_sync(0xffffffffu, p, 16);
    p += __shfl_xor_sync(0xffffffffu, p, 8);
    p += __shfl_xor_sync(0xffffffffu, p, 4);
    p += __shfl_xor_sync(0xffffffffu, p, 2);
    p += __shfl_xor_sync(0xffffffffu, p, 1);
    if (lane == 0) red_sm[0][wrp] = p;
    __syncthreads();
    if (tid == 0) {
        float v = 0.f;
        for (int wi = 0; wi < 16; wi++) v += red_sm[0][wi];
        g_logits[bid] = v + bo[bid];
        __threadfence();
        atomicAdd(&g_bar2, 1u);
    }

    // hidden part of output
    int hoff = -1;
    if (out_size >= OUTN + H) hoff = OUTN;
    else if (out_size == H)   hoff = 0;
    if (hoff >= 0 && tid < COLS) {
        int j = jbase + tid;
        outp[hoff + j] = x_sm[j];
    }

    // log_softmax of 128 logits, CTA 0 only
    if (bid == 0 && out_size != H) {
        if (tid == 0) {
            while (ld_acq_u(&g_bar2) < (unsigned)GRID) { }
        }
        __syncthreads();
        float v = (tid < OUTN) ? g_logits[tid] : -INFINITY;
        float m = v;
        m = fmaxf(m, __shfl_xor_sync(0xffffffffu, m, 16));
        m = fmaxf(m, __shfl_xor_sync(0xffffffffu, m, 8));
        m = fmaxf(m, __shfl_xor_sync(0xffffffffu, m, 4));
        m = fmaxf(m, __shfl_xor_sync(0xffffffffu, m, 2));
        m = fmaxf(m, __shfl_xor_sync(0xffffffffu, m, 1));
        if (lane == 0) red_sm[1][wrp] = m;
        __syncthreads();
        if (tid == 0) {
            float mm = red_sm[1][0];
            for (int wi = 1; wi < 16; wi++) mm = fmaxf(mm, red_sm[1][wi]);
            red_sm[1][32] = mm;
        }
        __syncthreads();
        float mm = red_sm[1][32];
        float e = (tid < OUTN) ? expf(v - mm) : 0.f;
        e += __shfl_xor_sync(0xffffffffu, e, 16);
        e += __shfl_xor_sync(0xffffffffu, e, 8);
        e += __shfl_xor_sync(0xffffffffu, e, 4);
        e += __shfl_xor_sync(0xffffffffu, e, 2);
        e += __shfl_xor_sync(0xffffffffu, e, 1);
        if (lane == 0) red_sm[1][wrp + 34] = e;
        __syncthreads();
        if (tid == 0) {
            float ss = 0.f;
            for (int wi = 0; wi < 16; wi++) ss += red_sm[1][wi + 34];
            red_sm[1][33] = logf(ss);
        }
        __syncthreads();
        if (tid < OUTN) outp[tid] = v - mm - red_sm[1][33];
    }
}

extern "C" void kernel_launch(void* const* d_in, const int* in_sizes, int n_in,
                              void* d_out, int out_size) {
    const float* x  = (const float*)d_in[0];
    const float* h0 = (const float*)d_in[1];
    const float* W  = (const float*)d_in[2];
    const float* b  = (const float*)d_in[3];
    const float* Wo = (const float*)d_in[4];
    const float* bo = (const float*)d_in[5];
    const int*   mk = (const int*)d_in[6];

    awk_init_kernel<<<8, 256>>>(h0);
    awk_kernel<<<GRID, NT>>>(x, h0, W, b, Wo, bo, mk, (float*)d_out, out_size);
}

// round 10
// speedup vs baseline: 1.4040x; 1.4040x over previous
#include <cuda_runtime.h>
#include <math.h>

#define GRID   128
#define NT     512
#define COLS   16
#define H      2048
#define D      16
#define TMAX   4096
#define OUTN   128
#define NGRP   8            // 8 arrival counters, 16 CTAs each
#define WSTRIDE ((size_t)2049 * 2048)

// Persistent device state (no allocation).
// g_ctr[g*32] reaches 16*(t+1) when all 16 CTAs of group g finished step t.
__device__ __align__(128) unsigned g_ctr[NGRP * 32];   // 128B-spaced counters
__device__ unsigned g_bar2;                            // epilogue logits barrier
__device__ __align__(16) float g_h[2][H];
__device__ float g_logits[OUTN];

__global__ void awk_init_kernel(const float* __restrict__ h0) {
    int i = blockIdx.x * blockDim.x + threadIdx.x;
    if (i < H) g_h[0][i] = h0[i];
    if (i < NGRP * 32) g_ctr[i] = 0u;
    if (i == 0) g_bar2 = 0u;
}

__device__ __forceinline__ unsigned ld_acq_u(const unsigned* p) {
    unsigned v;
    asm volatile("ld.acquire.gpu.u32 %0, [%1];" : "=r"(v) : "l"(p) : "memory");
    return v;
}

#define FMA2(acc, hh, ww) \
    asm("fma.rn.f32x2 %0, %1, %2, %3;" : "=l"(acc) : "l"(hh), "l"(ww), "l"(acc))
#define UNPK(fx, fy, a) \
    asm("mov.b64 {%0, %1}, %2;" : "=f"(fx), "=f"(fy) : "l"(a))

__global__ __launch_bounds__(NT, 1)
void awk_kernel(const float* __restrict__ x_in,    // [4096]
                const float* __restrict__ Wg,      // [16, 2049, 2048]
                const float* __restrict__ bg,      // [16, 2048]
                const float* __restrict__ Wo,      // [2048, 128]
                const float* __restrict__ bo,      // [128]
                const int*   __restrict__ markers, // [16]
                float* __restrict__ outp, int out_size)
{
    __shared__ float x_sm[TMAX];                 // input scalars; reused for final h
    __shared__ float h_sm[16 * 136];             // per-warp padded h chunks
    __shared__ float red_sm[2][256];             // step-parity double-buffered partials
    __shared__ int   cum_sm[D + 4];

    const int tid   = threadIdx.x;
    const int bid   = blockIdx.x;
    const int lane  = tid & 31;
    const int wrp   = tid >> 5;
    const int c     = tid & 15;     // column within CTA
    const int s     = tid >> 4;     // k-segment 0..31 (64 k-values each)
    const int jbase = bid * COLS;
    const int grp   = bid >> 4;     // arrival counter group

    for (int i = tid; i < TMAX; i += NT) x_sm[i] = x_in[i];
    if (tid == 0) {
        int a = 0;
        for (int l = 0; l < D; l++) { a += markers[l]; cum_sm[l] = a; }
        cum_sm[D] = (a < TMAX) ? a : TMAX;
    }
    __syncthreads();
    const int S = cum_sm[D];

    unsigned long long w2[32];     // 64 weights packed as 32 f32x2
    float w0 = 0.f, bb = 0.f;
    int layer = 0, next_b = 0;

    for (int step = 0; step < S; ++step) {
        // ---- layer switch: refill register weights (64B-coalesced direct LDG) ----
        if (step == next_b) {
            while (step >= cum_sm[layer]) layer++;
            next_b = cum_sm[layer];
            const float* Wl = Wg + (size_t)layer * WSTRIDE + 2048 + jbase + c;
            #pragma unroll 8
            for (int q = 0; q < 32; q++) {
                float wa = Wl[(size_t)(64 * s + 2 * q)     * 2048];
                float wb = Wl[(size_t)(64 * s + 2 * q + 1) * 2048];
                asm("mov.b64 %0, {%1, %2};" : "=l"(w2[q]) : "f"(wa), "f"(wb));
            }
            if (tid < COLS) {
                w0 = Wg[(size_t)layer * WSTRIDE + jbase + tid];
                bb = bg[layer * H + jbase + tid];
            }
        }

        // ---- detect: warp 0, lanes 0-7 each acquire-load ONE counter (parallel RTTs) ----
        if (wrp == 0) {
            const unsigned tgt = 16u * (unsigned)step;   // all groups done with step-1
            bool ok;
            do {
                ok = (lane >= NGRP) || (ld_acq_u(&g_ctr[lane * 32]) >= tgt);
            } while (!__all_sync(0xffffffffu, ok));
        }
        __syncthreads();                  // (A) propagate acquire CTA-wide

        const int buf = step & 1;

        // ---- warp-private h chunk: GMEM(L2, bypass L1) -> SMEM ----
        {
            float4 hv = __ldcg((const float4*)(g_h[buf] + wrp * 128 + lane * 4));
            *(float4*)(&h_sm[wrp * 136 + (lane >> 4) * 68 + (lane & 15) * 4]) = hv;
        }
        __syncwarp();

        // ---- partial dot: 32 packed f32x2 FMAs, 16 LDS.128 ----
        unsigned long long a0 = 0ull, a1 = 0ull, a2 = 0ull, a3 = 0ull;
        const ulonglong2* hp = (const ulonglong2*)(&h_sm[wrp * 136 + (s & 1) * 68]);
        #pragma unroll
        for (int q = 0; q < 16; q++) {
            ulonglong2 hq = hp[q];
            if (q & 1) { FMA2(a2, hq.x, w2[2 * q]); FMA2(a3, hq.y, w2[2 * q + 1]); }
            else       { FMA2(a0, hq.x, w2[2 * q]); FMA2(a1, hq.y, w2[2 * q + 1]); }
        }
        float f0x, f0y, f1x, f1y, f2x, f2y, f3x, f3y;
        UNPK(f0x, f0y, a0); UNPK(f1x, f1y, a1);
        UNPK(f2x, f2y, a2); UNPK(f3x, f3y, a3);
        float acc = ((f0x + f0y) + (f1x + f1y)) + ((f2x + f2y) + (f3x + f3y));

        acc += __shfl_xor_sync(0xffffffffu, acc, 16);
        if (lane < 16) red_sm[buf][wrp * 16 + lane] = acc;
        __syncthreads();                  // (B) partials ready; h reads done

        // ---- final reduce + relu + publish + arrive (warp 0) ----
        if (wrp == 0) {
            const int half = lane >> 4;
            const float xs = x_sm[step];
            float v = 0.f;
            #pragma unroll
            for (int wi = 0; wi < 8; wi++) v += red_sm[buf][(half * 8 + wi) * 16 + c];
            v += __shfl_xor_sync(0xffffffffu, v, 16);
            if (lane < 16) {
                v = fmaf(xs, w0, v) + bb;
                v = fmaxf(v, 0.f);
                g_h[buf ^ 1][jbase + lane] = v;
            }
            __syncwarp();
            if (lane == 0) {
                __threadfence();                         // release h slice
                atomicAdd(&g_ctr[grp * 32], 1u);         // 16-deep chain per group, 8 in parallel
            }
        }
    }

    // ======== epilogue ========
    if (wrp == 0) {
        const unsigned tgt = 16u * (unsigned)S;
        bool ok;
        do {
            ok = (lane >= NGRP) || (ld_acq_u(&g_ctr[lane * 32]) >= tgt);
        } while (!__all_sync(0xffffffffu, ok));
    }
    __syncthreads();
    {
        const int buf = S & 1;
        float4 hv = __ldcg((const float4*)(g_h[buf] + wrp * 128 + lane * 4));
        *(float4*)(&x_sm[wrp * 128 + lane * 4]) = hv;   // full final h, contiguous
    }
    __syncthreads();

    // logit for output o = bid  (GRID == OUTN)
    float p = 0.f;
    #pragma unroll
    for (int r = 0; r < H / NT; r++) {
        int i = r * NT + tid;
        p += x_sm[i] * Wo[(size_t)i * OUTN + bid];
    }
    p += __shfl_xor_sync(0xffffffffu, p, 16);
    p += __shfl_xor_sync(0xffffffffu, p, 8);
    p += __shfl_xor_sync(0xffffffffu, p, 4);
    p += __shfl_xor_sync(0xffffffffu, p, 2);
    p += __shfl_xor_sync(0xffffffffu, p, 1);
    if (lane == 0) red_sm[0][wrp] = p;
    __syncthreads();
    if (tid == 0) {
        float v = 0.f;
        for (int wi = 0; wi < 16; wi++) v += red_sm[0][wi];
        g_logits[bid] = v + bo[bid];
        __threadfence();
        atomicAdd(&g_bar2, 1u);
    }

    // hidden part of output
    int hoff = -1;
    if (out_size >= OUTN + H) hoff = OUTN;
    else if (out_size == H)   hoff = 0;
    if (hoff >= 0 && tid < COLS) {
        int j = jbase + tid;
        outp[hoff + j] = x_sm[j];
    }

    // log_softmax of 128 logits, CTA 0 only
    if (bid == 0 && out_size != H) {
        if (tid == 0) {
            while (ld_acq_u(&g_bar2) < (unsigned)GRID) { }
        }
        __syncthreads();
        float v = (tid < OUTN) ? g_logits[tid] : -INFINITY;
        float m = v;
        m = fmaxf(m, __shfl_xor_sync(0xffffffffu, m, 16));
        m = fmaxf(m, __shfl_xor_sync(0xffffffffu, m, 8));
        m = fmaxf(m, __shfl_xor_sync(0xffffffffu, m, 4));
        m = fmaxf(m, __shfl_xor_sync(0xffffffffu, m, 2));
        m = fmaxf(m, __shfl_xor_sync(0xffffffffu, m, 1));
        if (lane == 0) red_sm[1][wrp] = m;
        __syncthreads();
        if (tid == 0) {
            float mm = red_sm[1][0];
            for (int wi = 1; wi < 16; wi++) mm = fmaxf(mm, red_sm[1][wi]);
            red_sm[1][32] = mm;
        }
        __syncthreads();
        float mm = red_sm[1][32];
        float e = (tid < OUTN) ? expf(v - mm) : 0.f;
        e += __shfl_xor_sync(0xffffffffu, e, 16);
        e += __shfl_xor_sync(0xffffffffu, e, 8);
        e += __shfl_xor_sync(0xffffffffu, e, 4);
        e += __shfl_xor_sync(0xffffffffu, e, 2);
        e += __shfl_xor_sync(0xffffffffu, e, 1);
        if (lane == 0) red_sm[1][wrp + 34] = e;
        __syncthreads();
        if (tid == 0) {
            float ss = 0.f;
            for (int wi = 0; wi < 16; wi++) ss += red_sm[1][wi + 34];
            red_sm[1][33] = logf(ss);
        }
        __syncthreads();
        if (tid < OUTN) outp[tid] = v - mm - red_sm[1][33];
    }
}

extern "C" void kernel_launch(void* const* d_in, const int* in_sizes, int n_in,
                              void* d_out, int out_size) {
    const float* x  = (const float*)d_in[0];
    const float* h0 = (const float*)d_in[1];
    const float* W  = (const float*)d_in[2];
    const float* b  = (const float*)d_in[3];
    const float* Wo = (const float*)d_in[4];
    const float* bo = (const float*)d_in[5];
    const int*   mk = (const int*)d_in[6];

    awk_init_kernel<<<8, 256>>>(h0);
    awk_kernel<<<GRID, NT>>>(x, W, b, Wo, bo, mk, (float*)d_out, out_size);
}